// round 10
// baseline (speedup 1.0000x reference)
#include <cuda_runtime.h>
#include <cuda_fp16.h>

#define BSZ    2048
#define TT     128
#define NN     256
#define MM     256
#define GG4    1024
#define B_TILE 16
#define NBLK   (BSZ / B_TILE)  /* 128 */
#define NTHR   1024

// ---------------- device scratch ----------------
__device__ __half g_Ux[(size_t)BSZ * TT * NN];       // [b][s][n] fp16, 134 MB
__device__ float4 g_Wt [128 * 1024];                 // [k4][r] : 4 consecutive k of row r (r = g*256+m)
__device__ float4 g_WtE[128 * 128];                  // [k4][s] : 4 consecutive k of W_e row s

// ---------------- fast math ----------------
__device__ __forceinline__ float ex2f(float x) {
    float r; asm("ex2.approx.f32 %0, %1;" : "=f"(r) : "f"(x)); return r;
}
__device__ __forceinline__ float rcpf(float x) {
    float r; asm("rcp.approx.f32 %0, %1;" : "=f"(r) : "f"(x)); return r;
}
#define L2E 1.4426950408889634f
__device__ __forceinline__ float tanh_fast(float x) {      // precise path (cell update)
    float t = ex2f(2.0f * L2E * x);
    return 1.0f - 2.0f * rcpf(t + 1.0f);
}
__device__ __forceinline__ float sigmoid_fast(float x) {
    return rcpf(1.0f + ex2f(-L2E * x));
}
__device__ __forceinline__ unsigned tanh2_h(unsigned x) {  // f16x2 hw tanh (attention only)
    unsigned r; asm("tanh.approx.f16x2 %0, %1;" : "=r"(r) : "r"(x)); return r;
}

// ---------------- packed f32x2 ----------------
typedef unsigned long long u64;
__device__ __forceinline__ u64 pack2(float a, float b) {
    u64 r; asm("mov.b64 %0, {%1, %2};" : "=l"(r) : "f"(a), "f"(b)); return r;
}
__device__ __forceinline__ void unpack2(u64 v, float& a, float& b) {
    asm("mov.b64 {%0, %1}, %2;" : "=f"(a), "=f"(b) : "l"(v));
}
__device__ __forceinline__ u64 ffma2(u64 a, u64 b, u64 c) {
    u64 d; asm("fma.rn.f32x2 %0, %1, %2, %3;" : "=l"(d) : "l"(a), "l"(b), "l"(c)); return d;
}
__device__ __forceinline__ float pair_sum(u64 v) {
    float a, b; unpack2(v, a, b); return a + b;
}
__device__ __forceinline__ void stcs(float* p, float v) {
    asm volatile("st.global.cs.f32 [%0], %1;" :: "l"(p), "f"(v) : "memory");
}

// =====================================================================
// Kernel 1: Ux precompute (+ weight transpose in trailing blocks).
// =====================================================================
__global__ void __launch_bounds__(256, 1) ux_kernel(
    const float* __restrict__ x,    const float* __restrict__ U_e,
    const float* __restrict__ W_ih, const float* __restrict__ W_hh,
    const float* __restrict__ W_e)
{
    if (blockIdx.x >= BSZ) {   // ---- transpose duty ----
        int idx = (blockIdx.x - BSZ) * 256 + threadIdx.x;
        if (idx < 128 * 1024) {
            int k4 = idx >> 10, r = idx & 1023;
            float4 v = (k4 < 64) ? ((const float4*)W_ih)[r * 64 + k4]
                                 : ((const float4*)W_hh)[r * 64 + (k4 - 64)];
            g_Wt[idx] = v;
        } else {
            int j = idx - 128 * 1024;      // 0..16383
            int k4 = j >> 7, s = j & 127;
            g_WtE[j] = ((const float4*)W_e)[s * 128 + k4];
        }
        return;
    }

    extern __shared__ float sm[];
    float* x_s  = sm;                    // [TT][NN]
    u64*   U2_s = (u64*)(sm + TT * NN);  // [64 s-pairs][128 t]
    float* U2f  = (float*)U2_s;

    const int b   = blockIdx.x;
    const int tid = threadIdx.x;

    const float4* xg = (const float4*)(x + (size_t)b * TT * NN);
    float4* xs4 = (float4*)x_s;
    for (int i = tid; i < TT * NN / 4; i += 256) xs4[i] = xg[i];

    for (int i = tid; i < TT * TT / 4; i += 256) {
        float4 v = ((const float4*)U_e)[i];
        int s  = i >> 5;
        int t0 = (i & 31) * 4;
        #pragma unroll
        for (int q = 0; q < 4; q++)
            U2f[(((s >> 1) * 128) + (t0 + q)) * 2 + (s & 1)] = (&v.x)[q];
    }
    __syncthreads();

    const int n = tid;
    for (int chunk = 0; chunk < 8; chunk++) {
        u64 acc[8];
        #pragma unroll
        for (int i = 0; i < 8; i++) acc[i] = 0ull;
        #pragma unroll 2
        for (int t = 0; t < TT; t++) {
            float xv = x_s[t * NN + n];
            u64 xp = pack2(xv, xv);
            #pragma unroll
            for (int i = 0; i < 8; i++)
                acc[i] = ffma2(U2_s[(chunk * 8 + i) * 128 + t], xp, acc[i]);
        }
        #pragma unroll
        for (int i = 0; i < 8; i++) {
            float a, bb; unpack2(acc[i], a, bb);
            #pragma unroll
            for (int h = 0; h < 2; h++) {
                float v = h ? bb : a;
                int s = chunk * 16 + 2 * i + h;
                float vn = __shfl_down_sync(0xffffffffu, v, 1);
                if ((n & 1) == 0) {
                    __half2 hv = __floats2half2_rn(v, vn);
                    *((__half2*)(g_Ux + ((size_t)b * TT + s) * NN + n)) = hv;
                }
            }
        }
    }
}

// =====================================================================
// Kernel 2: persistent recurrence. 128 blocks x 16 batches, 1024 threads.
// 32 warps/CTA for latency hiding; per-thread work halved vs R8.
// =====================================================================
__global__ void __launch_bounds__(NTHR, 1) rec_kernel(
    const float* __restrict__ V_e,
    const float* __restrict__ b_ih, const float* __restrict__ b_hh,
    float* __restrict__ out)
{
    extern __shared__ float sm[];
    float*    h_s   = sm;                      // [B_TILE][NN]
    float*    c_s   = h_s  + B_TILE * NN;      // [B_TILE][NN]
    float*    ex_s  = c_s  + B_TILE * NN;      // [B_TILE][NN]  e, then xt in place
    float*    bs_s  = ex_s + B_TILE * NN;      // [GG4]
    float*    V_s   = bs_s + GG4;              // [TT]
    unsigned* whs2  = (unsigned*)(V_s + TT);   // [TT][B_TILE] half2(w,w)

    const int tid = threadIdx.x;
    const int b0  = blockIdx.x * B_TILE;

    for (int i = tid; i < 2 * B_TILE * NN; i += NTHR) h_s[i] = 0.0f;  // h_s + c_s
    for (int i = tid; i < TT;  i += NTHR) V_s[i]  = V_e[i];
    for (int i = tid; i < GG4; i += NTHR) bs_s[i] = b_ih[i] + b_hh[i];
    __syncthreads();

    // phase A: thread = (sI, 2 batches)
    const int sI  = tid & 127;
    const int jA  = (tid >> 7) * 2;            // 0,2,..,14
    // phase B: thread = (n-pair, 2 batches); jg warp-uniform
    const int np  = tid & 127;
    const int n0  = np * 2;
    const int jg  = tid >> 7;                  // 0..7
    // phase C: warp = batch (warps 0..15 active)
    const int warp = tid >> 5, lane = tid & 31;
    // phase D: thread = (m, 4 batches)
    const int mD  = tid & 255;
    const int jD0 = (tid >> 8) * 4;            // 0,4,8,12

    const __half2* ux2[2];
    #pragma unroll
    for (int jj = 0; jj < 2; jj++)
        ux2[jj] = (const __half2*)(g_Ux + ((size_t)(b0 + jg * 2 + jj) * TT) * NN + n0);

    const float4* wr = g_Wt + mD;

    for (int t = 0; t < TT; t++) {
        // ---------- Phase A: whs[sI][j] = [h;c] . W_e[sI]  (k-paired f32x2) ----------
        {
            u64 acc0 = 0ull, acc1 = 0ull;
            #pragma unroll 4
            for (int k4 = 0; k4 < 64; k4++) {
                ulonglong2 wp = *(const ulonglong2*)&g_WtE[k4 * 128 + sI];
                ulonglong2 s0 = *(const ulonglong2*)&h_s[(jA + 0) * NN + k4 * 4];
                ulonglong2 s1 = *(const ulonglong2*)&h_s[(jA + 1) * NN + k4 * 4];
                acc0 = ffma2(wp.x, s0.x, acc0); acc0 = ffma2(wp.y, s0.y, acc0);
                acc1 = ffma2(wp.x, s1.x, acc1); acc1 = ffma2(wp.y, s1.y, acc1);
            }
            #pragma unroll 4
            for (int k4 = 64; k4 < 128; k4++) {
                ulonglong2 wp = *(const ulonglong2*)&g_WtE[k4 * 128 + sI];
                ulonglong2 s0 = *(const ulonglong2*)&c_s[(jA + 0) * NN + (k4 - 64) * 4];
                ulonglong2 s1 = *(const ulonglong2*)&c_s[(jA + 1) * NN + (k4 - 64) * 4];
                acc0 = ffma2(wp.x, s0.x, acc0); acc0 = ffma2(wp.y, s0.y, acc0);
                acc1 = ffma2(wp.x, s1.x, acc1); acc1 = ffma2(wp.y, s1.y, acc1);
            }
            __half2 p0 = __half2half2(__float2half_rn(pair_sum(acc0)));
            __half2 p1 = __half2half2(__float2half_rn(pair_sum(acc1)));
            uint2 pk = make_uint2(*(unsigned*)&p0, *(unsigned*)&p1);
            *(uint2*)&whs2[sI * B_TILE + jA] = pk;
        }
        __syncthreads();

        // ---------- Phase B: e[j][n] = sum_s V[s] * tanh(Ux + whs)  (fp16 stream) ----------
        {
            float ex0[2] = {0, 0}, ex1[2] = {0, 0};
            #pragma unroll 4
            for (int s = 0; s < TT; s++) {
                uint2 wpk = *(const uint2*)&whs2[s * B_TILE + jg * 2];  // broadcast
                float vs = V_s[s];
                #pragma unroll
                for (int jj = 0; jj < 2; jj++) {
                    __half2 u   = ux2[jj][s * (NN / 2)];
                    __half2 wv  = *(__half2*)(((unsigned*)&wpk) + jj);
                    __half2 arg = __hadd2(u, wv);
                    unsigned th = tanh2_h(*(unsigned*)&arg);
                    float2 f = __half22float2(*(__half2*)&th);
                    ex0[jj] = fmaf(vs, f.x, ex0[jj]);
                    ex1[jj] = fmaf(vs, f.y, ex1[jj]);
                }
            }
            #pragma unroll
            for (int jj = 0; jj < 2; jj++) {
                float2 v = make_float2(ex0[jj], ex1[jj]);
                *(float2*)&ex_s[(jg * 2 + jj) * NN + n0] = v;
            }
        }
        __syncthreads();

        // ---------- Phase C: softmax over n, xt = alpha * e  (warps 0..15) ----------
        if (warp < B_TILE) {
            const int j = warp;
            float ev[8];
            float mx = -3.4e38f;
            #pragma unroll
            for (int i = 0; i < 8; i++) {
                ev[i] = ex_s[j * NN + lane + 32 * i];
                mx = fmaxf(mx, ev[i]);
            }
            #pragma unroll
            for (int o = 16; o > 0; o >>= 1) mx = fmaxf(mx, __shfl_xor_sync(0xffffffffu, mx, o));
            float ax[8], sum = 0.0f;
            #pragma unroll
            for (int i = 0; i < 8; i++) { ax[i] = ex2f((ev[i] - mx) * L2E); sum += ax[i]; }
            #pragma unroll
            for (int o = 16; o > 0; o >>= 1) sum += __shfl_xor_sync(0xffffffffu, sum, o);
            float inv = rcpf(sum);
            #pragma unroll
            for (int i = 0; i < 8; i++)
                ex_s[j * NN + lane + 32 * i] = (ax[i] * inv) * ev[i];
        }
        __syncthreads();

        // ---------- Phase D: gates, two gate-pair passes (acc = 16 regs/pass) ----------
        {
            float giv[4], gfv[4], ggv[4], gov[4];

            // pass 1: gates i (rows 0..255) and f (rows 256..511)
            {
                u64 a0[4], a1[4];
                u64 bi = pack2(bs_s[0 * MM + mD], 0.0f);
                u64 bf = pack2(bs_s[1 * MM + mD], 0.0f);
                #pragma unroll
                for (int jj = 0; jj < 4; jj++) { a0[jj] = bi; a1[jj] = bf; }
                #pragma unroll 4
                for (int k4 = 0; k4 < 64; k4++) {
                    ulonglong2 w0 = *(const ulonglong2*)&wr[k4 * 1024 +   0];
                    ulonglong2 w1 = *(const ulonglong2*)&wr[k4 * 1024 + 256];
                    #pragma unroll
                    for (int jj = 0; jj < 4; jj++) {
                        ulonglong2 sp = *(const ulonglong2*)&ex_s[(jD0 + jj) * NN + k4 * 4];
                        a0[jj] = ffma2(w0.x, sp.x, a0[jj]);
                        a0[jj] = ffma2(w0.y, sp.y, a0[jj]);
                        a1[jj] = ffma2(w1.x, sp.x, a1[jj]);
                        a1[jj] = ffma2(w1.y, sp.y, a1[jj]);
                    }
                }
                #pragma unroll 4
                for (int k4 = 64; k4 < 128; k4++) {
                    ulonglong2 w0 = *(const ulonglong2*)&wr[k4 * 1024 +   0];
                    ulonglong2 w1 = *(const ulonglong2*)&wr[k4 * 1024 + 256];
                    #pragma unroll
                    for (int jj = 0; jj < 4; jj++) {
                        ulonglong2 sp = *(const ulonglong2*)&h_s[(jD0 + jj) * NN + (k4 - 64) * 4];
                        a0[jj] = ffma2(w0.x, sp.x, a0[jj]);
                        a0[jj] = ffma2(w0.y, sp.y, a0[jj]);
                        a1[jj] = ffma2(w1.x, sp.x, a1[jj]);
                        a1[jj] = ffma2(w1.y, sp.y, a1[jj]);
                    }
                }
                #pragma unroll
                for (int jj = 0; jj < 4; jj++) { giv[jj] = pair_sum(a0[jj]); gfv[jj] = pair_sum(a1[jj]); }
            }

            // pass 2: gates g (rows 512..767) and o (rows 768..1023)
            {
                u64 a0[4], a1[4];
                u64 bg = pack2(bs_s[2 * MM + mD], 0.0f);
                u64 bo = pack2(bs_s[3 * MM + mD], 0.0f);
                #pragma unroll
                for (int jj = 0; jj < 4; jj++) { a0[jj] = bg; a1[jj] = bo; }
                #pragma unroll 4
                for (int k4 = 0; k4 < 64; k4++) {
                    ulonglong2 w0 = *(const ulonglong2*)&wr[k4 * 1024 + 512];
                    ulonglong2 w1 = *(const ulonglong2*)&wr[k4 * 1024 + 768];
                    #pragma unroll
                    for (int jj = 0; jj < 4; jj++) {
                        ulonglong2 sp = *(const ulonglong2*)&ex_s[(jD0 + jj) * NN + k4 * 4];
                        a0[jj] = ffma2(w0.x, sp.x, a0[jj]);
                        a0[jj] = ffma2(w0.y, sp.y, a0[jj]);
                        a1[jj] = ffma2(w1.x, sp.x, a1[jj]);
                        a1[jj] = ffma2(w1.y, sp.y, a1[jj]);
                    }
                }
                #pragma unroll 4
                for (int k4 = 64; k4 < 128; k4++) {
                    ulonglong2 w0 = *(const ulonglong2*)&wr[k4 * 1024 + 512];
                    ulonglong2 w1 = *(const ulonglong2*)&wr[k4 * 1024 + 768];
                    #pragma unroll
                    for (int jj = 0; jj < 4; jj++) {
                        ulonglong2 sp = *(const ulonglong2*)&h_s[(jD0 + jj) * NN + (k4 - 64) * 4];
                        a0[jj] = ffma2(w0.x, sp.x, a0[jj]);
                        a0[jj] = ffma2(w0.y, sp.y, a0[jj]);
                        a1[jj] = ffma2(w1.x, sp.x, a1[jj]);
                        a1[jj] = ffma2(w1.y, sp.y, a1[jj]);
                    }
                }
                #pragma unroll
                for (int jj = 0; jj < 4; jj++) { ggv[jj] = pair_sum(a0[jj]); gov[jj] = pair_sum(a1[jj]); }
            }

            float cold[4];
            #pragma unroll
            for (int jj = 0; jj < 4; jj++) cold[jj] = c_s[(jD0 + jj) * NN + mD];
            __syncthreads();   // all reads of h_s/ex_s/c_s complete before writes

            #pragma unroll
            for (int jj = 0; jj < 4; jj++) {
                float cn = sigmoid_fast(gfv[jj]) * cold[jj]
                         + sigmoid_fast(giv[jj]) * tanh_fast(ggv[jj]);
                float hn = sigmoid_fast(gov[jj]) * tanh_fast(cn);
                c_s[(jD0 + jj) * NN + mD] = cn;
                h_s[(jD0 + jj) * NN + mD] = hn;
                stcs(&out[(size_t)(b0 + jD0 + jj) * (MM * TT) + (size_t)mD * TT + t], hn);
            }
        }
        __syncthreads();   // state visible before next step
    }
}

extern "C" void kernel_launch(void* const* d_in, const int* in_sizes, int n_in,
                              void* d_out, int out_size)
{
    const float* x    = (const float*)d_in[0];
    const float* W_e  = (const float*)d_in[1];
    const float* U_e  = (const float*)d_in[2];
    const float* V_e  = (const float*)d_in[3];
    const float* W_ih = (const float*)d_in[4];
    const float* W_hh = (const float*)d_in[5];
    const float* b_ih = (const float*)d_in[6];
    const float* b_hh = (const float*)d_in[7];
    float* out = (float*)d_out;

    const int smem1 = (TT * NN) * 4 + 64 * 128 * 8;                        // 196608
    const int smem2 = (3 * B_TILE * NN + GG4 + TT) * 4 + TT * B_TILE * 4;  // ~62 KB

    cudaFuncSetAttribute(ux_kernel,  cudaFuncAttributeMaxDynamicSharedMemorySize, smem1);
    cudaFuncSetAttribute(rec_kernel, cudaFuncAttributeMaxDynamicSharedMemorySize, smem2);

    ux_kernel<<<BSZ + 576, 256, smem1>>>(x, U_e, W_ih, W_hh, W_e);
    rec_kernel<<<NBLK, NTHR, smem2>>>(V_e, b_ih, b_hh, out);
}

// round 12
// speedup vs baseline: 1.5402x; 1.5402x over previous
#include <cuda_runtime.h>
#include <cuda_fp16.h>

#define BSZ    2048
#define TT     128
#define NN     256
#define MM     256
#define GG4    1024
#define B_TILE 16
#define SST    20              /* padded j-stride for k-major state  */
#define NBLK   (BSZ / B_TILE)  /* 128 */
#define NTHR   1024

// ---------------- device scratch ----------------
__device__ __half g_Ux[(size_t)BSZ * TT * NN];       // [b][s][n] fp16, 134 MB
__device__ float4 g_Wt [128 * 1024];                 // [k4][r] : 4 consecutive k of row r (r = g*256+m)
__device__ float4 g_WtE[128 * 128];                  // [k4][s] : 4 consecutive k of W_e row s

// ---------------- fast math ----------------
__device__ __forceinline__ float ex2f(float x) {
    float r; asm("ex2.approx.f32 %0, %1;" : "=f"(r) : "f"(x)); return r;
}
__device__ __forceinline__ float rcpf(float x) {
    float r; asm("rcp.approx.f32 %0, %1;" : "=f"(r) : "f"(x)); return r;
}
#define L2E 1.4426950408889634f
__device__ __forceinline__ float tanh_fast(float x) {      // precise path (cell update)
    float t = ex2f(2.0f * L2E * x);
    return 1.0f - 2.0f * rcpf(t + 1.0f);
}
__device__ __forceinline__ float sigmoid_fast(float x) {
    return rcpf(1.0f + ex2f(-L2E * x));
}
__device__ __forceinline__ unsigned tanh2_h(unsigned x) {  // f16x2 hw tanh (attention only)
    unsigned r; asm("tanh.approx.f16x2 %0, %1;" : "=r"(r) : "r"(x)); return r;
}

// ---------------- packed f32x2 ----------------
typedef unsigned long long u64;
__device__ __forceinline__ u64 pack2(float a, float b) {
    u64 r; asm("mov.b64 %0, {%1, %2};" : "=l"(r) : "f"(a), "f"(b)); return r;
}
__device__ __forceinline__ void unpack2(u64 v, float& a, float& b) {
    asm("mov.b64 {%0, %1}, %2;" : "=f"(a), "=f"(b) : "l"(v));
}
__device__ __forceinline__ u64 ffma2(u64 a, u64 b, u64 c) {
    u64 d; asm("fma.rn.f32x2 %0, %1, %2, %3;" : "=l"(d) : "l"(a), "l"(b), "l"(c)); return d;
}
__device__ __forceinline__ u64 add2(u64 a, u64 b) {
    u64 d; asm("add.rn.f32x2 %0, %1, %2;" : "=l"(d) : "l"(a), "l"(b)); return d;
}
__device__ __forceinline__ void stcs(float* p, float v) {
    asm volatile("st.global.cs.f32 [%0], %1;" :: "l"(p), "f"(v) : "memory");
}

// =====================================================================
// Kernel 1: Ux precompute (+ weight transpose in trailing blocks).
// =====================================================================
__global__ void __launch_bounds__(256, 1) ux_kernel(
    const float* __restrict__ x,    const float* __restrict__ U_e,
    const float* __restrict__ W_ih, const float* __restrict__ W_hh,
    const float* __restrict__ W_e)
{
    if (blockIdx.x >= BSZ) {   // ---- transpose duty ----
        int idx = (blockIdx.x - BSZ) * 256 + threadIdx.x;
        if (idx < 128 * 1024) {
            int k4 = idx >> 10, r = idx & 1023;
            float4 v = (k4 < 64) ? ((const float4*)W_ih)[r * 64 + k4]
                                 : ((const float4*)W_hh)[r * 64 + (k4 - 64)];
            g_Wt[idx] = v;
        } else {
            int j = idx - 128 * 1024;      // 0..16383
            int k4 = j >> 7, s = j & 127;
            g_WtE[j] = ((const float4*)W_e)[s * 128 + k4];
        }
        return;
    }

    extern __shared__ float sm[];
    float* x_s  = sm;                    // [TT][NN]
    u64*   U2_s = (u64*)(sm + TT * NN);  // [64 s-pairs][128 t]
    float* U2f  = (float*)U2_s;

    const int b   = blockIdx.x;
    const int tid = threadIdx.x;

    const float4* xg = (const float4*)(x + (size_t)b * TT * NN);
    float4* xs4 = (float4*)x_s;
    for (int i = tid; i < TT * NN / 4; i += 256) xs4[i] = xg[i];

    for (int i = tid; i < TT * TT / 4; i += 256) {
        float4 v = ((const float4*)U_e)[i];
        int s  = i >> 5;
        int t0 = (i & 31) * 4;
        #pragma unroll
        for (int q = 0; q < 4; q++)
            U2f[(((s >> 1) * 128) + (t0 + q)) * 2 + (s & 1)] = (&v.x)[q];
    }
    __syncthreads();

    const int n = tid;
    for (int chunk = 0; chunk < 8; chunk++) {
        u64 acc[8];
        #pragma unroll
        for (int i = 0; i < 8; i++) acc[i] = 0ull;
        #pragma unroll 2
        for (int t = 0; t < TT; t++) {
            float xv = x_s[t * NN + n];
            u64 xp = pack2(xv, xv);
            #pragma unroll
            for (int i = 0; i < 8; i++)
                acc[i] = ffma2(U2_s[(chunk * 8 + i) * 128 + t], xp, acc[i]);
        }
        #pragma unroll
        for (int i = 0; i < 8; i++) {
            float a, bb; unpack2(acc[i], a, bb);
            #pragma unroll
            for (int h = 0; h < 2; h++) {
                float v = h ? bb : a;
                int s = chunk * 16 + 2 * i + h;
                float vn = __shfl_down_sync(0xffffffffu, v, 1);
                if ((n & 1) == 0) {
                    __half2 hv = __floats2half2_rn(v, vn);
                    *((__half2*)(g_Ux + ((size_t)b * TT + s) * NN + n)) = hv;
                }
            }
        }
    }
}

// =====================================================================
// Kernel 2: persistent recurrence. 128 blocks x 16 batches, 1024 threads.
// State k-major [k][SST] (j-paired reads). Phase A k-split, phase D
// gate-pair/batch-half split -> minimal L1 wavefronts.
// =====================================================================
__global__ void __launch_bounds__(NTHR, 1) rec_kernel(
    const float* __restrict__ V_e,
    const float* __restrict__ b_ih, const float* __restrict__ b_hh,
    float* __restrict__ out)
{
    extern __shared__ float sm[];
    float*    h_s   = sm;                       // [MM][SST]  5120
    float*    c_s   = h_s  + MM * SST;          // [MM][SST]  5120
    float*    xt_s  = c_s  + MM * SST;          // [NN][SST]  5120
    float*    e_s   = xt_s + NN * SST;          // [B_TILE][NN] 4096
    float*    bs_s  = e_s  + B_TILE * NN;       // [GG4]      1024
    float*    V_s   = bs_s + GG4;               // [TT]       128
    unsigned* whs2  = (unsigned*)(V_s + TT);    // [TT][B_TILE] half2(w,w)  2048 words
    u64*      un_s  = (u64*)(whs2 + TT * B_TILE); // union: A-red [8][128][8] u64 / D-gates [4][8][256] u64 (64 KB)

    const int tid = threadIdx.x;
    const int b0  = blockIdx.x * B_TILE;

    for (int i = tid; i < 2 * MM * SST; i += NTHR) h_s[i] = 0.0f;  // h_s + c_s
    for (int i = tid; i < TT;  i += NTHR) V_s[i]  = V_e[i];
    for (int i = tid; i < GG4; i += NTHR) bs_s[i] = b_ih[i] + b_hh[i];
    __syncthreads();

    // phase A: thread = (sA, k-eighth kg)
    const int sA  = tid & 127;
    const int kg  = tid >> 7;                   // 0..7
    const float* aState = (kg < 4) ? h_s : c_s;
    const int    aK4    = (kg & 3) * 16;        // local k4 base inside h or c
    // phase A reduce: thread = (rs, j-pair rp)
    const int rs  = tid & 127;
    const int rp  = tid >> 7;                   // 0..7
    // phase B: thread = (n-pair, 2 batches); jg warp-uniform
    const int np  = tid & 127;
    const int n0  = np * 2;
    const int jg  = tid >> 7;                   // 0..7
    // phase C: warp = batch (warps 0..15 active)
    const int warp = tid >> 5, lane = tid & 31;
    // phase D accum: thread = (mD, gate-pair gp, batch-half jh)
    const int mD  = tid & 255;
    const int gp  = (tid >> 8) & 1;
    const int jh  = tid >> 9;                   // 0 or 1
    const int jb  = jh * 8;
    // phase D epilogue: thread = (mD, j-quad)
    const int j0  = (tid >> 8) * 4;             // 0,4,8,12

    const __half2* ux2[2];
    #pragma unroll
    for (int jj = 0; jj < 2; jj++)
        ux2[jj] = (const __half2*)(g_Ux + ((size_t)(b0 + jg * 2 + jj) * TT) * NN + n0);

    const float4* wrA = g_Wt + gp * 512 + mD;        // gate gp*2
    const float4* wrB = g_Wt + gp * 512 + 256 + mD;  // gate gp*2+1
    const u64 bpA = pack2(bs_s[gp * 512 + mD],        bs_s[gp * 512 + mD]);
    const u64 bpB = pack2(bs_s[gp * 512 + 256 + mD],  bs_s[gp * 512 + 256 + mD]);

    for (int t = 0; t < TT; t++) {
        // ---------- Phase A1: partial whs, k-split over 8 groups ----------
        {
            u64 acc[8];
            #pragma unroll
            for (int p = 0; p < 8; p++) acc[p] = 0ull;
            #pragma unroll 2
            for (int i = 0; i < 16; i++) {
                const int k4g = kg * 16 + i;               // global weight k4
                float4 w = g_WtE[k4g * 128 + sA];
                #pragma unroll
                for (int q = 0; q < 4; q++) {
                    const int k = (aK4 + i) * 4 + q;       // local state index
                    const float* st = &aState[k * SST];
                    ulonglong2 s0 = *(const ulonglong2*)&st[0];
                    ulonglong2 s1 = *(const ulonglong2*)&st[4];
                    ulonglong2 s2 = *(const ulonglong2*)&st[8];
                    ulonglong2 s3 = *(const ulonglong2*)&st[12];
                    float wq = (&w.x)[q];
                    u64 wp = pack2(wq, wq);
                    acc[0] = ffma2(wp, s0.x, acc[0]);
                    acc[1] = ffma2(wp, s0.y, acc[1]);
                    acc[2] = ffma2(wp, s1.x, acc[2]);
                    acc[3] = ffma2(wp, s1.y, acc[3]);
                    acc[4] = ffma2(wp, s2.x, acc[4]);
                    acc[5] = ffma2(wp, s2.y, acc[5]);
                    acc[6] = ffma2(wp, s3.x, acc[6]);
                    acc[7] = ffma2(wp, s3.y, acc[7]);
                }
            }
            u64* red = &un_s[(kg * 128 + sA) * 8];
            #pragma unroll
            for (int p = 0; p < 8; p++) red[p] = acc[p];
        }
        __syncthreads();

        // ---------- Phase A2: reduce 8 partials -> whs2 (half2 broadcast pairs) ----------
        {
            u64 sum = un_s[(0 * 128 + rs) * 8 + rp];
            #pragma unroll
            for (int g2 = 1; g2 < 8; g2++)
                sum = add2(sum, un_s[(g2 * 128 + rs) * 8 + rp]);
            float f0, f1; unpack2(sum, f0, f1);
            __half2 p0 = __half2half2(__float2half_rn(f0));
            __half2 p1 = __half2half2(__float2half_rn(f1));
            whs2[rs * B_TILE + rp * 2 + 0] = *(unsigned*)&p0;
            whs2[rs * B_TILE + rp * 2 + 1] = *(unsigned*)&p1;
        }
        __syncthreads();

        // ---------- Phase B: e[j][n] = sum_s V[s] * tanh(Ux + whs)  (fp16 stream) ----------
        {
            float ex0[2] = {0, 0}, ex1[2] = {0, 0};
            #pragma unroll 4
            for (int s = 0; s < TT; s++) {
                uint2 wpk = *(const uint2*)&whs2[s * B_TILE + jg * 2];  // broadcast
                float vs = V_s[s];
                #pragma unroll
                for (int jj = 0; jj < 2; jj++) {
                    __half2 u   = ux2[jj][s * (NN / 2)];
                    __half2 wv  = *(__half2*)(((unsigned*)&wpk) + jj);
                    __half2 arg = __hadd2(u, wv);
                    unsigned th = tanh2_h(*(unsigned*)&arg);
                    float2 f = __half22float2(*(__half2*)&th);
                    ex0[jj] = fmaf(vs, f.x, ex0[jj]);
                    ex1[jj] = fmaf(vs, f.y, ex1[jj]);
                }
            }
            #pragma unroll
            for (int jj = 0; jj < 2; jj++) {
                float2 v = make_float2(ex0[jj], ex1[jj]);
                *(float2*)&e_s[(jg * 2 + jj) * NN + n0] = v;
            }
        }
        __syncthreads();

        // ---------- Phase C: softmax over n, xt = alpha * e -> xt_s [n][SST] ----------
        if (warp < B_TILE) {
            const int j = warp;
            float ev[8];
            float mx = -3.4e38f;
            #pragma unroll
            for (int i = 0; i < 8; i++) {
                ev[i] = e_s[j * NN + lane + 32 * i];
                mx = fmaxf(mx, ev[i]);
            }
            #pragma unroll
            for (int o = 16; o > 0; o >>= 1) mx = fmaxf(mx, __shfl_xor_sync(0xffffffffu, mx, o));
            float ax[8], sum = 0.0f;
            #pragma unroll
            for (int i = 0; i < 8; i++) { ax[i] = ex2f((ev[i] - mx) * L2E); sum += ax[i]; }
            #pragma unroll
            for (int o = 16; o > 0; o >>= 1) sum += __shfl_xor_sync(0xffffffffu, sum, o);
            float inv = rcpf(sum);
            #pragma unroll
            for (int i = 0; i < 8; i++)
                xt_s[(lane + 32 * i) * SST + j] = (ax[i] * inv) * ev[i];
        }
        __syncthreads();

        // ---------- Phase D accum: thread = (mD, gate-pair, batch-half of 8 j) ----------
        {
            u64 a0[4], a1[4];
            #pragma unroll
            for (int p = 0; p < 4; p++) { a0[p] = bpA; a1[p] = bpB; }

            #pragma unroll 2
            for (int k4 = 0; k4 < 64; k4++) {          // k < 256 : xt
                float4 w0 = wrA[k4 * 1024];
                float4 w1 = wrB[k4 * 1024];
                #pragma unroll
                for (int q = 0; q < 4; q++) {
                    const int k = k4 * 4 + q;
                    ulonglong2 sa = *(const ulonglong2*)&xt_s[k * SST + jb];
                    ulonglong2 sb = *(const ulonglong2*)&xt_s[k * SST + jb + 4];
                    float wq0 = (&w0.x)[q], wq1 = (&w1.x)[q];
                    u64 wp0 = pack2(wq0, wq0), wp1 = pack2(wq1, wq1);
                    a0[0] = ffma2(wp0, sa.x, a0[0]);
                    a0[1] = ffma2(wp0, sa.y, a0[1]);
                    a0[2] = ffma2(wp0, sb.x, a0[2]);
                    a0[3] = ffma2(wp0, sb.y, a0[3]);
                    a1[0] = ffma2(wp1, sa.x, a1[0]);
                    a1[1] = ffma2(wp1, sa.y, a1[1]);
                    a1[2] = ffma2(wp1, sb.x, a1[2]);
                    a1[3] = ffma2(wp1, sb.y, a1[3]);
                }
            }
            #pragma unroll 2
            for (int k4 = 64; k4 < 128; k4++) {        // k >= 256 : h
                float4 w0 = wrA[k4 * 1024];
                float4 w1 = wrB[k4 * 1024];
                #pragma unroll
                for (int q = 0; q < 4; q++) {
                    const int k = (k4 - 64) * 4 + q;
                    ulonglong2 sa = *(const ulonglong2*)&h_s[k * SST + jb];
                    ulonglong2 sb = *(const ulonglong2*)&h_s[k * SST + jb + 4];
                    float wq0 = (&w0.x)[q], wq1 = (&w1.x)[q];
                    u64 wp0 = pack2(wq0, wq0), wp1 = pack2(wq1, wq1);
                    a0[0] = ffma2(wp0, sa.x, a0[0]);
                    a0[1] = ffma2(wp0, sa.y, a0[1]);
                    a0[2] = ffma2(wp0, sb.x, a0[2]);
                    a0[3] = ffma2(wp0, sb.y, a0[3]);
                    a1[0] = ffma2(wp1, sa.x, a1[0]);
                    a1[1] = ffma2(wp1, sa.y, a1[1]);
                    a1[2] = ffma2(wp1, sb.x, a1[2]);
                    a1[3] = ffma2(wp1, sb.y, a1[3]);
                }
            }
            // gates union layout: [gate 4][jp 8][mD 256] u64 (j-pairs)
            u64* guA = &un_s[((gp * 2 + 0) * 8 + jh * 4) * 256 + mD];
            u64* guB = &un_s[((gp * 2 + 1) * 8 + jh * 4) * 256 + mD];
            #pragma unroll
            for (int p = 0; p < 4; p++) { guA[p * 256] = a0[p]; guB[p * 256] = a1[p]; }
        }
        __syncthreads();

        // ---------- Phase D epilogue: thread = (mD, 4 j) ----------
        {
            float gv[4][4];    // [gate][jj]
            #pragma unroll
            for (int g = 0; g < 4; g++) {
                u64 v0 = un_s[(g * 8 + (j0 >> 1) + 0) * 256 + mD];
                u64 v1 = un_s[(g * 8 + (j0 >> 1) + 1) * 256 + mD];
                unpack2(v0, gv[g][0], gv[g][1]);
                unpack2(v1, gv[g][2], gv[g][3]);
            }
            float4 coldv = *(const float4*)&c_s[mD * SST + j0];
            float cnv[4], hnv[4];
            #pragma unroll
            for (int jj = 0; jj < 4; jj++) {
                float cold = (&coldv.x)[jj];
                float cn = sigmoid_fast(gv[1][jj]) * cold
                         + sigmoid_fast(gv[0][jj]) * tanh_fast(gv[2][jj]);
                float hn = sigmoid_fast(gv[3][jj]) * tanh_fast(cn);
                cnv[jj] = cn; hnv[jj] = hn;
                stcs(&out[(size_t)(b0 + j0 + jj) * (MM * TT) + (size_t)mD * TT + t], hn);
            }
            *(float4*)&c_s[mD * SST + j0] = make_float4(cnv[0], cnv[1], cnv[2], cnv[3]);
            *(float4*)&h_s[mD * SST + j0] = make_float4(hnv[0], hnv[1], hnv[2], hnv[3]);
        }
        __syncthreads();   // state visible before next step
    }
}

extern "C" void kernel_launch(void* const* d_in, const int* in_sizes, int n_in,
                              void* d_out, int out_size)
{
    const float* x    = (const float*)d_in[0];
    const float* W_e  = (const float*)d_in[1];
    const float* U_e  = (const float*)d_in[2];
    const float* V_e  = (const float*)d_in[3];
    const float* W_ih = (const float*)d_in[4];
    const float* W_hh = (const float*)d_in[5];
    const float* b_ih = (const float*)d_in[6];
    const float* b_hh = (const float*)d_in[7];
    float* out = (float*)d_out;

    const int smem1 = (TT * NN) * 4 + 64 * 128 * 8;                        // 196608
    // h + c + xt + e + bias + V + whs2 + 64KB union
    const int smem2 = (2 * MM * SST + NN * SST + B_TILE * NN + GG4 + TT) * 4
                    + TT * B_TILE * 4 + 8192 * 8;                           // 155,904 B

    cudaFuncSetAttribute(ux_kernel,  cudaFuncAttributeMaxDynamicSharedMemorySize, smem1);
    cudaFuncSetAttribute(rec_kernel, cudaFuncAttributeMaxDynamicSharedMemorySize, smem2);

    ux_kernel<<<BSZ + 576, 256, smem1>>>(x, U_e, W_ih, W_hh, W_e);
    rec_kernel<<<NBLK, NTHR, smem2>>>(V_e, b_ih, b_hh, out);
}

// round 13
// speedup vs baseline: 1.6977x; 1.1022x over previous
#include <cuda_runtime.h>
#include <cuda_fp16.h>
#include <cuda_bf16.h>

#define BSZ    2048
#define TT     128
#define NN     256
#define MM     256
#define GG4    1024
#define B_TILE 16
#define SST    20              /* padded j-stride for k-major state  */
#define NBLK   (BSZ / B_TILE)  /* 128 */
#define NTHR   1024

// ---------------- device scratch ----------------
__device__ __half g_Ux[(size_t)BSZ * TT * NN];   // [b][s][n] fp16, 134 MB
__device__ uint4  g_Wtb [64 * 1024];             // [k8][r] : 8 consecutive bf16 k of row r (r = g*256+m), 1 MB
__device__ uint4  g_WtEb[16 * 128];              // [k8][s] : 8 consecutive bf16 k of W_e row s, 32 KB

// ---------------- fast math ----------------
__device__ __forceinline__ float ex2f(float x) {
    float r; asm("ex2.approx.f32 %0, %1;" : "=f"(r) : "f"(x)); return r;
}
__device__ __forceinline__ float rcpf(float x) {
    float r; asm("rcp.approx.f32 %0, %1;" : "=f"(r) : "f"(x)); return r;
}
#define L2E 1.4426950408889634f
__device__ __forceinline__ float tanh_fast(float x) {      // precise path (cell update)
    float t = ex2f(2.0f * L2E * x);
    return 1.0f - 2.0f * rcpf(t + 1.0f);
}
__device__ __forceinline__ float sigmoid_fast(float x) {
    return rcpf(1.0f + ex2f(-L2E * x));
}
__device__ __forceinline__ unsigned tanh2_h(unsigned x) {  // f16x2 hw tanh (attention only)
    unsigned r; asm("tanh.approx.f16x2 %0, %1;" : "=r"(r) : "r"(x)); return r;
}

// ---------------- packed f32x2 ----------------
typedef unsigned long long u64;
__device__ __forceinline__ u64 pack2(float a, float b) {
    u64 r; asm("mov.b64 %0, {%1, %2};" : "=l"(r) : "f"(a), "f"(b)); return r;
}
__device__ __forceinline__ void unpack2(u64 v, float& a, float& b) {
    asm("mov.b64 {%0, %1}, %2;" : "=f"(a), "=f"(b) : "l"(v));
}
__device__ __forceinline__ u64 ffma2(u64 a, u64 b, u64 c) {
    u64 d; asm("fma.rn.f32x2 %0, %1, %2, %3;" : "=l"(d) : "l"(a), "l"(b), "l"(c)); return d;
}
__device__ __forceinline__ u64 add2(u64 a, u64 b) {
    u64 d; asm("add.rn.f32x2 %0, %1, %2;" : "=l"(d) : "l"(a), "l"(b)); return d;
}
__device__ __forceinline__ void stcs(float* p, float v) {
    asm volatile("st.global.cs.f32 [%0], %1;" :: "l"(p), "f"(v) : "memory");
}
// bf16 helpers: word = (k_odd_bf16 << 16) | k_even_bf16
__device__ __forceinline__ unsigned pack_bf2(float lo, float hi) {
    __nv_bfloat162 h = __floats2bfloat162_rn(lo, hi);
    return *(unsigned*)&h;
}
// duplicate-packed f32x2 (w,w) from a bf16 bit field
__device__ __forceinline__ u64 wdup(unsigned fbits) {
    float f = __uint_as_float(fbits);
    return pack2(f, f);
}

// =====================================================================
// Kernel 1: Ux precompute (+ bf16 weight transpose in trailing blocks).
// =====================================================================
__global__ void __launch_bounds__(256, 1) ux_kernel(
    const float* __restrict__ x,    const float* __restrict__ U_e,
    const float* __restrict__ W_ih, const float* __restrict__ W_hh,
    const float* __restrict__ W_e)
{
    if (blockIdx.x >= BSZ) {   // ---- transpose + bf16 convert ----
        int idx = (blockIdx.x - BSZ) * 256 + threadIdx.x;
        if (idx < 64 * 1024) {
            int k8 = idx >> 10, r = idx & 1023;
            const float* src = (k8 < 32) ? (W_ih + r * 256 + k8 * 8)
                                         : (W_hh + r * 256 + (k8 - 32) * 8);
            float4 a = *(const float4*)(src);
            float4 b = *(const float4*)(src + 4);
            uint4 o;
            o.x = pack_bf2(a.x, a.y); o.y = pack_bf2(a.z, a.w);
            o.z = pack_bf2(b.x, b.y); o.w = pack_bf2(b.z, b.w);
            g_Wtb[idx] = o;
        } else if (idx < 64 * 1024 + 16 * 128) {
            int j = idx - 64 * 1024;       // j = k8*128 + s
            int k8 = j >> 7, s = j & 127;
            const float* src = W_e + s * 512 + k8 * 8;
            float4 a = *(const float4*)(src);
            float4 b = *(const float4*)(src + 4);
            uint4 o;
            o.x = pack_bf2(a.x, a.y); o.y = pack_bf2(a.z, a.w);
            o.z = pack_bf2(b.x, b.y); o.w = pack_bf2(b.z, b.w);
            g_WtEb[j] = o;
        }
        return;
    }

    extern __shared__ float sm[];
    float* x_s  = sm;                    // [TT][NN]
    u64*   U2_s = (u64*)(sm + TT * NN);  // [64 s-pairs][128 t]
    float* U2f  = (float*)U2_s;

    const int b   = blockIdx.x;
    const int tid = threadIdx.x;

    const float4* xg = (const float4*)(x + (size_t)b * TT * NN);
    float4* xs4 = (float4*)x_s;
    for (int i = tid; i < TT * NN / 4; i += 256) xs4[i] = xg[i];

    for (int i = tid; i < TT * TT / 4; i += 256) {
        float4 v = ((const float4*)U_e)[i];
        int s  = i >> 5;
        int t0 = (i & 31) * 4;
        #pragma unroll
        for (int q = 0; q < 4; q++)
            U2f[(((s >> 1) * 128) + (t0 + q)) * 2 + (s & 1)] = (&v.x)[q];
    }
    __syncthreads();

    const int n = tid;
    for (int chunk = 0; chunk < 8; chunk++) {
        u64 acc[8];
        #pragma unroll
        for (int i = 0; i < 8; i++) acc[i] = 0ull;
        #pragma unroll 2
        for (int t = 0; t < TT; t++) {
            float xv = x_s[t * NN + n];
            u64 xp = pack2(xv, xv);
            #pragma unroll
            for (int i = 0; i < 8; i++)
                acc[i] = ffma2(U2_s[(chunk * 8 + i) * 128 + t], xp, acc[i]);
        }
        #pragma unroll
        for (int i = 0; i < 8; i++) {
            float a, bb; unpack2(acc[i], a, bb);
            #pragma unroll
            for (int h = 0; h < 2; h++) {
                float v = h ? bb : a;
                int s = chunk * 16 + 2 * i + h;
                float vn = __shfl_down_sync(0xffffffffu, v, 1);
                if ((n & 1) == 0) {
                    __half2 hv = __floats2half2_rn(v, vn);
                    *((__half2*)(g_Ux + ((size_t)b * TT + s) * NN + n)) = hv;
                }
            }
        }
    }
}

// =====================================================================
// Kernel 2: persistent recurrence. 128 blocks x 16 batches, 1024 threads.
// bf16 weights (half the LDG wavefronts + L2 traffic), ALU-pipe unpack.
// =====================================================================
__global__ void __launch_bounds__(NTHR, 1) rec_kernel(
    const float* __restrict__ V_e,
    const float* __restrict__ b_ih, const float* __restrict__ b_hh,
    float* __restrict__ out)
{
    extern __shared__ float sm[];
    float*    h_s   = sm;                       // [MM][SST]  5120
    float*    c_s   = h_s  + MM * SST;          // [MM][SST]  5120
    float*    xt_s  = c_s  + MM * SST;          // [NN][SST]  5120
    float*    e_s   = xt_s + NN * SST;          // [B_TILE][NN] 4096
    float*    bs_s  = e_s  + B_TILE * NN;       // [GG4]      1024
    float*    V_s   = bs_s + GG4;               // [TT]       128
    unsigned* whs2  = (unsigned*)(V_s + TT);    // [TT][B_TILE] half2(w,w)
    u64*      un_s  = (u64*)(whs2 + TT * B_TILE); // union: A-red [8 kg][8 jp][128 s] / D-gates [4][8][256] (64 KB)

    const int tid = threadIdx.x;
    const int b0  = blockIdx.x * B_TILE;

    for (int i = tid; i < 2 * MM * SST; i += NTHR) h_s[i] = 0.0f;  // h_s + c_s
    for (int i = tid; i < TT;  i += NTHR) V_s[i]  = V_e[i];
    for (int i = tid; i < GG4; i += NTHR) bs_s[i] = b_ih[i] + b_hh[i];
    __syncthreads();

    // phase A: thread = (sA, k-eighth kg)
    const int sA  = tid & 127;
    const int kg  = tid >> 7;                   // 0..7
    const float* aState = (kg < 4) ? h_s : c_s;
    const int    aKBase = (kg & 3) * 64;        // local k base inside h or c
    // phase A reduce: thread = (rs, j-pair rp)
    const int rs  = tid & 127;
    const int rp  = tid >> 7;                   // 0..7
    // phase B: thread = (n-pair, 2 batches); jg warp-uniform
    const int np  = tid & 127;
    const int n0  = np * 2;
    const int jg  = tid >> 7;                   // 0..7
    // phase C: warp = batch (warps 0..15 active)
    const int warp = tid >> 5, lane = tid & 31;
    // phase D accum: thread = (mD, gate-pair gp, batch-half jh)
    const int mD  = tid & 255;
    const int gp  = (tid >> 8) & 1;
    const int jh  = tid >> 9;                   // 0 or 1
    const int jb  = jh * 8;
    // phase D epilogue: thread = (mD, j-quad)
    const int j0  = (tid >> 8) * 4;             // 0,4,8,12

    const __half2* ux2[2];
    #pragma unroll
    for (int jj = 0; jj < 2; jj++)
        ux2[jj] = (const __half2*)(g_Ux + ((size_t)(b0 + jg * 2 + jj) * TT) * NN + n0);

    const uint4* wA = g_Wtb + gp * 512 + mD;        // gate gp*2 row (bf16 x8 per load)
    const uint4* wB = g_Wtb + gp * 512 + 256 + mD;  // gate gp*2+1 row
    const u64 bpA = pack2(bs_s[gp * 512 + mD],        bs_s[gp * 512 + mD]);
    const u64 bpB = pack2(bs_s[gp * 512 + 256 + mD],  bs_s[gp * 512 + 256 + mD]);

    for (int t = 0; t < TT; t++) {
        // ---------- Phase A1: partial whs, k-split over 8 groups (bf16 weights) ----------
        {
            u64 acc[8];
            #pragma unroll
            for (int p = 0; p < 8; p++) acc[p] = 0ull;
            #pragma unroll 2
            for (int i = 0; i < 8; i++) {                    // 8 k8-groups of 8 k
                uint4 wv = g_WtEb[(kg * 8 + i) * 128 + sA];
                #pragma unroll
                for (int q = 0; q < 4; q++) {
                    unsigned w32 = ((const unsigned*)&wv)[q];
                    #pragma unroll
                    for (int sub = 0; sub < 2; sub++) {
                        u64 wp = wdup(sub ? (w32 & 0xFFFF0000u) : (w32 << 16));
                        const int k = aKBase + i * 8 + q * 2 + sub;
                        const float* st = &aState[k * SST];
                        ulonglong2 s0 = *(const ulonglong2*)&st[0];
                        ulonglong2 s1 = *(const ulonglong2*)&st[4];
                        ulonglong2 s2 = *(const ulonglong2*)&st[8];
                        ulonglong2 s3 = *(const ulonglong2*)&st[12];
                        acc[0] = ffma2(wp, s0.x, acc[0]);
                        acc[1] = ffma2(wp, s0.y, acc[1]);
                        acc[2] = ffma2(wp, s1.x, acc[2]);
                        acc[3] = ffma2(wp, s1.y, acc[3]);
                        acc[4] = ffma2(wp, s2.x, acc[4]);
                        acc[5] = ffma2(wp, s2.y, acc[5]);
                        acc[6] = ffma2(wp, s3.x, acc[6]);
                        acc[7] = ffma2(wp, s3.y, acc[7]);
                    }
                }
            }
            // layout [kg][p][sA] so A2 reads are lane-coalesced
            #pragma unroll
            for (int p = 0; p < 8; p++) un_s[(kg * 8 + p) * 128 + sA] = acc[p];
        }
        __syncthreads();

        // ---------- Phase A2: reduce 8 partials -> whs2 (coalesced LDS.64) ----------
        {
            u64 sum = un_s[(0 * 8 + rp) * 128 + rs];
            #pragma unroll
            for (int g2 = 1; g2 < 8; g2++)
                sum = add2(sum, un_s[(g2 * 8 + rp) * 128 + rs]);
            float f0, f1; unpack2(sum, f0, f1);
            __half2 p0 = __half2half2(__float2half_rn(f0));
            __half2 p1 = __half2half2(__float2half_rn(f1));
            whs2[rs * B_TILE + rp * 2 + 0] = *(unsigned*)&p0;
            whs2[rs * B_TILE + rp * 2 + 1] = *(unsigned*)&p1;
        }
        __syncthreads();

        // ---------- Phase B: e[j][n] = sum_s V[s] * tanh(Ux + whs)  (fp16 stream) ----------
        {
            float ex0[2] = {0, 0}, ex1[2] = {0, 0};
            #pragma unroll 4
            for (int s = 0; s < TT; s++) {
                uint2 wpk = *(const uint2*)&whs2[s * B_TILE + jg * 2];  // broadcast
                float vs = V_s[s];
                #pragma unroll
                for (int jj = 0; jj < 2; jj++) {
                    __half2 u   = ux2[jj][s * (NN / 2)];
                    __half2 wv  = *(__half2*)(((unsigned*)&wpk) + jj);
                    __half2 arg = __hadd2(u, wv);
                    unsigned th = tanh2_h(*(unsigned*)&arg);
                    float2 f = __half22float2(*(__half2*)&th);
                    ex0[jj] = fmaf(vs, f.x, ex0[jj]);
                    ex1[jj] = fmaf(vs, f.y, ex1[jj]);
                }
            }
            #pragma unroll
            for (int jj = 0; jj < 2; jj++) {
                float2 v = make_float2(ex0[jj], ex1[jj]);
                *(float2*)&e_s[(jg * 2 + jj) * NN + n0] = v;
            }
        }
        __syncthreads();

        // ---------- Phase C: softmax over n, xt = alpha * e -> xt_s [n][SST] ----------
        if (warp < B_TILE) {
            const int j = warp;
            float ev[8];
            float mx = -3.4e38f;
            #pragma unroll
            for (int i = 0; i < 8; i++) {
                ev[i] = e_s[j * NN + lane + 32 * i];
                mx = fmaxf(mx, ev[i]);
            }
            #pragma unroll
            for (int o = 16; o > 0; o >>= 1) mx = fmaxf(mx, __shfl_xor_sync(0xffffffffu, mx, o));
            float ax[8], sum = 0.0f;
            #pragma unroll
            for (int i = 0; i < 8; i++) { ax[i] = ex2f((ev[i] - mx) * L2E); sum += ax[i]; }
            #pragma unroll
            for (int o = 16; o > 0; o >>= 1) sum += __shfl_xor_sync(0xffffffffu, sum, o);
            float inv = rcpf(sum);
            #pragma unroll
            for (int i = 0; i < 8; i++)
                xt_s[(lane + 32 * i) * SST + j] = (ax[i] * inv) * ev[i];
        }
        __syncthreads();

        // ---------- Phase D accum: thread = (mD, gate-pair, batch-half); bf16 weights ----------
        {
            u64 a0[4], a1[4];
            #pragma unroll
            for (int p = 0; p < 4; p++) { a0[p] = bpA; a1[p] = bpB; }

            #pragma unroll 2
            for (int k8 = 0; k8 < 32; k8++) {          // k < 256 : xt
                uint4 wv0 = wA[k8 * 1024];
                uint4 wv1 = wB[k8 * 1024];
                #pragma unroll
                for (int q = 0; q < 4; q++) {
                    unsigned u0 = ((const unsigned*)&wv0)[q];
                    unsigned u1 = ((const unsigned*)&wv1)[q];
                    #pragma unroll
                    for (int sub = 0; sub < 2; sub++) {
                        u64 wp0 = wdup(sub ? (u0 & 0xFFFF0000u) : (u0 << 16));
                        u64 wp1 = wdup(sub ? (u1 & 0xFFFF0000u) : (u1 << 16));
                        const int k = k8 * 8 + q * 2 + sub;
                        ulonglong2 sa = *(const ulonglong2*)&xt_s[k * SST + jb];
                        ulonglong2 sb = *(const ulonglong2*)&xt_s[k * SST + jb + 4];
                        a0[0] = ffma2(wp0, sa.x, a0[0]);
                        a0[1] = ffma2(wp0, sa.y, a0[1]);
                        a0[2] = ffma2(wp0, sb.x, a0[2]);
                        a0[3] = ffma2(wp0, sb.y, a0[3]);
                        a1[0] = ffma2(wp1, sa.x, a1[0]);
                        a1[1] = ffma2(wp1, sa.y, a1[1]);
                        a1[2] = ffma2(wp1, sb.x, a1[2]);
                        a1[3] = ffma2(wp1, sb.y, a1[3]);
                    }
                }
            }
            #pragma unroll 2
            for (int k8 = 32; k8 < 64; k8++) {         // k >= 256 : h
                uint4 wv0 = wA[k8 * 1024];
                uint4 wv1 = wB[k8 * 1024];
                #pragma unroll
                for (int q = 0; q < 4; q++) {
                    unsigned u0 = ((const unsigned*)&wv0)[q];
                    unsigned u1 = ((const unsigned*)&wv1)[q];
                    #pragma unroll
                    for (int sub = 0; sub < 2; sub++) {
                        u64 wp0 = wdup(sub ? (u0 & 0xFFFF0000u) : (u0 << 16));
                        u64 wp1 = wdup(sub ? (u1 & 0xFFFF0000u) : (u1 << 16));
                        const int k = (k8 - 32) * 8 + q * 2 + sub;
                        ulonglong2 sa = *(const ulonglong2*)&h_s[k * SST + jb];
                        ulonglong2 sb = *(const ulonglong2*)&h_s[k * SST + jb + 4];
                        a0[0] = ffma2(wp0, sa.x, a0[0]);
                        a0[1] = ffma2(wp0, sa.y, a0[1]);
                        a0[2] = ffma2(wp0, sb.x, a0[2]);
                        a0[3] = ffma2(wp0, sb.y, a0[3]);
                        a1[0] = ffma2(wp1, sa.x, a1[0]);
                        a1[1] = ffma2(wp1, sa.y, a1[1]);
                        a1[2] = ffma2(wp1, sb.x, a1[2]);
                        a1[3] = ffma2(wp1, sb.y, a1[3]);
                    }
                }
            }
            // gates union layout: [gate 4][jp 8][mD 256] u64 (j-pairs)
            u64* guA = &un_s[((gp * 2 + 0) * 8 + jh * 4) * 256 + mD];
            u64* guB = &un_s[((gp * 2 + 1) * 8 + jh * 4) * 256 + mD];
            #pragma unroll
            for (int p = 0; p < 4; p++) { guA[p * 256] = a0[p]; guB[p * 256] = a1[p]; }
        }
        __syncthreads();

        // ---------- Phase D epilogue: thread = (mD, 4 j) ----------
        {
            float gv[4][4];    // [gate][jj]
            #pragma unroll
            for (int g = 0; g < 4; g++) {
                u64 v0 = un_s[(g * 8 + (j0 >> 1) + 0) * 256 + mD];
                u64 v1 = un_s[(g * 8 + (j0 >> 1) + 1) * 256 + mD];
                unpack2(v0, gv[g][0], gv[g][1]);
                unpack2(v1, gv[g][2], gv[g][3]);
            }
            float4 coldv = *(const float4*)&c_s[mD * SST + j0];
            float cnv[4], hnv[4];
            #pragma unroll
            for (int jj = 0; jj < 4; jj++) {
                float cold = (&coldv.x)[jj];
                float cn = sigmoid_fast(gv[1][jj]) * cold
                         + sigmoid_fast(gv[0][jj]) * tanh_fast(gv[2][jj]);
                float hn = sigmoid_fast(gv[3][jj]) * tanh_fast(cn);
                cnv[jj] = cn; hnv[jj] = hn;
                stcs(&out[(size_t)(b0 + j0 + jj) * (MM * TT) + (size_t)mD * TT + t], hn);
            }
            *(float4*)&c_s[mD * SST + j0] = make_float4(cnv[0], cnv[1], cnv[2], cnv[3]);
            *(float4*)&h_s[mD * SST + j0] = make_float4(hnv[0], hnv[1], hnv[2], hnv[3]);
        }
        __syncthreads();   // state visible before next step
    }
}

extern "C" void kernel_launch(void* const* d_in, const int* in_sizes, int n_in,
                              void* d_out, int out_size)
{
    const float* x    = (const float*)d_in[0];
    const float* W_e  = (const float*)d_in[1];
    const float* U_e  = (const float*)d_in[2];
    const float* V_e  = (const float*)d_in[3];
    const float* W_ih = (const float*)d_in[4];
    const float* W_hh = (const float*)d_in[5];
    const float* b_ih = (const float*)d_in[6];
    const float* b_hh = (const float*)d_in[7];
    float* out = (float*)d_out;

    const int smem1 = (TT * NN) * 4 + 64 * 128 * 8;                        // 196608
    const int smem2 = (2 * MM * SST + NN * SST + B_TILE * NN + GG4 + TT) * 4
                    + TT * B_TILE * 4 + 8192 * 8;                           // 155,904 B

    cudaFuncSetAttribute(ux_kernel,  cudaFuncAttributeMaxDynamicSharedMemorySize, smem1);
    cudaFuncSetAttribute(rec_kernel, cudaFuncAttributeMaxDynamicSharedMemorySize, smem2);

    // trailing blocks: (64*1024 + 16*128) / 256 = 264
    ux_kernel<<<BSZ + 264, 256, smem1>>>(x, U_e, W_ih, W_hh, W_e);
    rec_kernel<<<NBLK, NTHR, smem2>>>(V_e, b_ih, b_hh, out);
}